// round 6
// baseline (speedup 1.0000x reference)
#include <cuda_runtime.h>

#define N_UNITS 8
#define M_ATOMS 1024
#define NPTS (N_UNITS * M_ATOMS)      // 8192
#define N_PAIRS 28
#define LOG2E 1.4426950408889634f
#define ALPHA 1.0f
#define LAMBDA1 0.5f

// ---------------- device scratch (allocation-free) ----------------
// g_u[idx] = (2*log2e*x, 2*log2e*y, 2*log2e*z, h) per transformed point
// g_vp: transposed j-side: per unit, per j-pair jj:
//   [jj][0]={x0,x1} [jj][1]={y0,y1} [jj][2]={z0,z1} [jj][3]={h0,h1}
__device__ float4 g_u[NPTS];
__device__ __align__(16) float g_vp[N_UNITS][M_ATOMS / 2][4][2];
__device__ float g_acc;           // zero-init; reset by last CTA each run
__device__ unsigned int g_count;  // zero-init; reset by last CTA each run

// pair (a,b) lookup, a < b
__constant__ unsigned char c_pa[N_PAIRS] =
    {0,0,0,0,0,0,0,1,1,1,1,1,1,2,2,2,2,2,3,3,3,3,4,4,4,5,5,6};
__constant__ unsigned char c_pb[N_PAIRS] =
    {1,2,3,4,5,6,7,2,3,4,5,6,7,3,4,5,6,7,4,5,6,7,5,6,7,6,7,7};

// ---------------- helpers ----------------
__device__ __forceinline__ float ex2_approx(float x) {
    float y;
    asm("ex2.approx.ftz.f32 %0, %1;" : "=f"(y) : "f"(x));
    return y;
}
__device__ __forceinline__ unsigned long long pack2(float a, float b) {
    unsigned long long r;
    asm("mov.b64 %0, {%1, %2};" : "=l"(r) : "f"(a), "f"(b));
    return r;
}
__device__ __forceinline__ void unpack2(unsigned long long p, float& lo, float& hi) {
    asm("mov.b64 {%0, %1}, %2;" : "=f"(lo), "=f"(hi) : "l"(p));
}
__device__ __forceinline__ unsigned long long fma2(unsigned long long a,
                                                   unsigned long long b,
                                                   unsigned long long c) {
    unsigned long long d;
    asm("fma.rn.f32x2 %0, %1, %2, %3;" : "=l"(d) : "l"(a), "l"(b), "l"(c));
    return d;
}
__device__ __forceinline__ unsigned long long add2(unsigned long long a,
                                                   unsigned long long b) {
    unsigned long long d;
    asm("add.rn.f32x2 %0, %1, %2;" : "=l"(d) : "l"(a), "l"(b));
    return d;
}

// ---------------- kernel 1: prep ----------------
__global__ void __launch_bounds__(256) k_prep(const float* __restrict__ pos,
                                              const float* __restrict__ eul,
                                              const float* __restrict__ coord)
{
    __shared__ float sR[12];
    int bid = blockIdx.x;
    int n = bid >> 2;
    int m = ((bid & 3) << 8) + threadIdx.x;

    if (threadIdx.x == 0) {
        float phi   = eul[3 * n + 0];
        float theta = eul[3 * n + 1];
        float psi   = eul[3 * n + 2];
        float sp, cp, st, ct, ss, cs;
        sincosf(phi,   &sp, &cp);
        sincosf(theta, &st, &ct);
        sincosf(psi,   &ss, &cs);
        sR[0] = cs * ct;
        sR[1] = cs * st * sp - ss * cp;
        sR[2] = cs * st * cp + ss * sp;
        sR[3] = ss * ct;
        sR[4] = ss * st * sp + cs * cp;
        sR[5] = ss * st * cp - cs * sp;
        sR[6] = -st;
        sR[7] = ct * sp;
        sR[8] = ct * cp;
        sR[9]  = pos[3 * n + 0];
        sR[10] = pos[3 * n + 1];
        sR[11] = pos[3 * n + 2];
    }
    __syncthreads();

    float cx = coord[3 * m + 0];
    float cy = coord[3 * m + 1];
    float cz = coord[3 * m + 2];

    float tx = fmaf(sR[0], cx, fmaf(sR[1], cy, fmaf(sR[2], cz, sR[9])));
    float ty = fmaf(sR[3], cx, fmaf(sR[4], cy, fmaf(sR[5], cz, sR[10])));
    float tz = fmaf(sR[6], cx, fmaf(sR[7], cy, fmaf(sR[8], cz, sR[11])));

    float sq = fmaf(tx, tx, fmaf(ty, ty, tz * tz));
    float h  = LOG2E * (0.5f - sq);

    int idx = n * M_ATOMS + m;
    g_u[idx] = make_float4(2.0f * LOG2E * tx,
                           2.0f * LOG2E * ty,
                           2.0f * LOG2E * tz, h);

    int jj = m >> 1, half = m & 1;
    g_vp[n][jj][0][half] = tx;
    g_vp[n][jj][1][half] = ty;
    g_vp[n][jj][2][half] = tz;
    g_vp[n][jj][3][half] = h;

    float t = sq;
    #pragma unroll
    for (int o = 16; o > 0; o >>= 1)
        t += __shfl_down_sync(0xFFFFFFFFu, t, o);
    __shared__ float ws[8];
    int lane = threadIdx.x & 31, wid = threadIdx.x >> 5;
    if (lane == 0) ws[wid] = t;
    __syncthreads();
    if (threadIdx.x == 0) {
        float s = 0.0f;
        #pragma unroll
        for (int w = 0; w < 8; w++) s += ws[w];
        atomicAdd(&g_acc, s * (1.0f / (float)N_UNITS));
    }

    if (bid == 0 && threadIdx.x == 32) {
        float sx = 0.0f, sy = 0.0f, sz = 0.0f;
        #pragma unroll
        for (int k = 0; k < N_UNITS; k++) {
            sx += pos[3 * k + 0];
            sy += pos[3 * k + 1];
            sz += pos[3 * k + 2];
        }
        atomicAdd(&g_acc, ALPHA * (sx * sx + sy * sy + sz * sz));
    }
}

// ---------------- kernel 2: pairs ----------------
// 28 pairs x 4 i-tiles(256) x 16 j-tiles(64) = 1792 CTAs, 128 threads.
// Each thread: 2 i-points x 64 j-points = 128 pairs, j packed 2-wide.
#define TPB 128
#define I_PER_THREAD 2
#define ITILE (TPB * I_PER_THREAD)   // 256
#define JTILE 64
#define NJJ (JTILE / 2)              // 32 packed iterations
#define PAIR_CTAS (N_PAIRS * (M_ATOMS / ITILE) * (M_ATOMS / JTILE))  // 1792

__global__ void __launch_bounds__(TPB, 12) k_pairs(float* __restrict__ out)
{
    int bid     = blockIdx.x;
    int pairIdx = bid >> 6;          // 64 tiles per pair
    int rem     = bid & 63;
    int iTile   = rem >> 4;          // 0..3
    int jTile   = rem & 15;          // 0..15

    int a = c_pa[pairIdx];
    int b = c_pb[pairIdx];

    int ibase = a * M_ATOMS + iTile * ITILE + threadIdx.x * I_PER_THREAD;
    int jj0   = jTile * NJJ;

    float4 u0 = __ldg(&g_u[ibase + 0]);
    float4 u1 = __ldg(&g_u[ibase + 1]);
    unsigned long long u0x = pack2(u0.x, u0.x), u0y = pack2(u0.y, u0.y),
                       u0z = pack2(u0.z, u0.z), u0w = pack2(u0.w, u0.w);
    unsigned long long u1x = pack2(u1.x, u1.x), u1y = pack2(u1.y, u1.y),
                       u1z = pack2(u1.z, u1.z), u1w = pack2(u1.w, u1.w);

    float acc0A = 0.f, acc0B = 0.f, acc1A = 0.f, acc1B = 0.f;

    const ulonglong2* __restrict__ vp = (const ulonglong2*)&g_vp[b][jj0][0][0];

    #pragma unroll 4
    for (int q = 0; q < NJJ; q++) {
        ulonglong2 P0 = vp[2 * q + 0];   // {xx, yy}
        ulonglong2 P1 = vp[2 * q + 1];   // {zz, ww}

        unsigned long long s0 =
            fma2(u0x, P0.x, fma2(u0y, P0.y, fma2(u0z, P1.x, add2(u0w, P1.y))));
        unsigned long long s1 =
            fma2(u1x, P0.x, fma2(u1y, P0.y, fma2(u1z, P1.x, add2(u1w, P1.y))));

        float lo0, hi0, lo1, hi1;
        unpack2(s0, lo0, hi0);
        unpack2(s1, lo1, hi1);
        acc0A += ex2_approx(lo0);
        acc0B += ex2_approx(hi0);
        acc1A += ex2_approx(lo1);
        acc1B += ex2_approx(hi1);
    }

    float t = (acc0A + acc0B) + (acc1A + acc1B);
    #pragma unroll
    for (int o = 16; o > 0; o >>= 1)
        t += __shfl_down_sync(0xFFFFFFFFu, t, o);

    __shared__ float ws[TPB / 32];
    int lane = threadIdx.x & 31, wid = threadIdx.x >> 5;
    if (lane == 0) ws[wid] = t;
    __syncthreads();

    if (threadIdx.x == 0) {
        float s = 0.0f;
        #pragma unroll
        for (int w = 0; w < TPB / 32; w++) s += ws[w];
        atomicAdd(&g_acc, LAMBDA1 * s);
        __threadfence();
        unsigned int nDone = atomicAdd(&g_count, 1u);
        if (nDone == PAIR_CTAS - 1) {
            float total = atomicExch(&g_acc, 0.0f);
            out[0] = total;
            atomicExch(&g_count, 0u);
        }
    }
}

extern "C" void kernel_launch(void* const* d_in, const int* in_sizes, int n_in,
                              void* d_out, int out_size)
{
    const float* positions    = (const float*)d_in[0];
    const float* euler_angles = (const float*)d_in[1];
    const float* coordinates  = (const float*)d_in[2];
    float* out = (float*)d_out;
    (void)in_sizes; (void)n_in; (void)out_size;

    k_prep<<<NPTS / 256, 256>>>(positions, euler_angles, coordinates);
    k_pairs<<<PAIR_CTAS, TPB>>>(out);
}